// round 2
// baseline (speedup 1.0000x reference)
#include <cuda_runtime.h>
#include <math.h>

#define NQ 14
#define BATCH 2048

struct Masks {
    unsigned S[NQ];   // S_w: row w of M^-1 (subset over u, bit u = 1<<u)
    unsigned T[NQ];   // T_w: column w of M
    int      k4[NQ];  // |S_w & T_w| mod 4
};

// Compile-time: compose the 28 CNOT permutations (GF(2)-linear), build M,
// invert it over GF(2), and extract S/T/k masks.
constexpr Masks compute_masks() {
    Masks ms{};
    unsigned M[NQ] = {};  // M[w]: bit u set iff bit_w(Q(e_u)) = 1
    for (int u = 0; u < NQ; ++u) {
        unsigned j = 1u << (13 - u);   // e_u in state-index bit convention (qubit w at pos 13-w)
        // final[i] = s0[P1(P2(...P28(i)))]; apply LAST listed perm first.
        // List order: step1 c0..c13, step2 c0..c13  ->  apply step2 c13 ... step1 c0
        for (int step = 2; step >= 1; --step)
            for (int c = NQ - 1; c >= 0; --c) {
                int t = (c + step) % NQ;
                if ((j >> (13 - c)) & 1u) j ^= 1u << (13 - t);
            }
        for (int w = 0; w < NQ; ++w)
            if ((j >> (13 - w)) & 1u) M[w] |= 1u << u;
    }
    // T_w = { r : M[r][w] = 1 }
    for (int w = 0; w < NQ; ++w) {
        unsigned t = 0;
        for (int r = 0; r < NQ; ++r)
            if ((M[r] >> w) & 1u) t |= 1u << r;
        ms.T[w] = t;
    }
    // Gauss-Jordan inversion over GF(2): [A|I] -> [I|A^-1]
    unsigned A[NQ] = {};
    unsigned I[NQ] = {};
    for (int r = 0; r < NQ; ++r) { A[r] = M[r]; I[r] = 1u << r; }
    for (int col = 0; col < NQ; ++col) {
        int piv = col;
        while (((A[piv] >> col) & 1u) == 0u) ++piv;  // CNOT network is invertible
        unsigned ta = A[col]; A[col] = A[piv]; A[piv] = ta;
        unsigned ti = I[col]; I[col] = I[piv]; I[piv] = ti;
        for (int r = 0; r < NQ; ++r)
            if (r != col && ((A[r] >> col) & 1u)) { A[r] ^= A[col]; I[r] ^= I[col]; }
    }
    for (int w = 0; w < NQ; ++w) ms.S[w] = I[w];
    for (int w = 0; w < NQ; ++w) {
        unsigned xm = ms.S[w] & ms.T[w];
        int cnt = 0;
        for (int b = 0; b < NQ; ++b) cnt += (int)((xm >> b) & 1u);
        ms.k4[w] = cnt & 3;
    }
    return ms;
}

__constant__ Masks d_MS = compute_masks();

__global__ void __launch_bounds__(256)
qulinear_kernel(const float* __restrict__ x, const float* __restrict__ u3,
                float* __restrict__ out) {
    // Batch-independent U3 coefficients, once per block.
    __shared__ float c1[NQ], c2[NQ], c3[NQ];
    int tid = threadIdx.x;
    if (tid < NQ) {
        float th  = u3[tid * 3 + 0];
        float lam = u3[tid * 3 + 2];   // phi (index 1) cancels in U3^dag Z U3
        float st, ct, sl, cl;
        sincosf(th, &st, &ct);
        sincosf(lam, &sl, &cl);
        float f;
        switch (d_MS.k4[tid]) {        // cos(lam + k*pi/2)
            case 0:  f =  cl; break;
            case 1:  f = -sl; break;
            case 2:  f = -cl; break;
            default: f =  sl; break;
        }
        c1[tid] = ct;
        c2[tid] = st * cl;
        c3[tid] = st * f;
    }
    __syncthreads();

    int b = blockIdx.x * blockDim.x + tid;
    if (b >= BATCH) return;

    float z[NQ], G[NQ], y[NQ];
#pragma unroll
    for (int u = 0; u < NQ; ++u) {
        float xv = x[b * NQ + u];
        float x2 = xv * xv;
        float i1 = rsqrtf(fmaf(xv, xv, 1.0f));   // 1/sqrt(1+x^2)
        float i2 = rsqrtf(fmaf(x2, x2, 1.0f));   // 1/sqrt(1+x^4)
        float gi = i1 * i2;
        z[u] = -xv * i1;
        G[u] = gi;
        y[u] = x2 * gi;
    }

#pragma unroll
    for (int w = 0; w < NQ; ++w) {
        unsigned Sm = d_MS.S[w];
        unsigned Tm = d_MS.T[w];
        float Zp = 1.0f, R1 = 1.0f, R2 = 1.0f;
#pragma unroll
        for (int u = 0; u < NQ; ++u) {
            bool iS = (Sm >> u) & 1u;
            bool iT = (Tm >> u) & 1u;
            if (iS) Zp *= z[u];
            if (iT) R1 *= G[u];
            float r2f = (iS && iT) ? y[u] : (iS ? z[u] : (iT ? G[u] : 1.0f));
            R2 *= r2f;
        }
        out[b * NQ + w] = c1[w] * Zp - c2[w] * R1 - c3[w] * R2;
    }
}

extern "C" void kernel_launch(void* const* d_in, const int* in_sizes, int n_in,
                              void* d_out, int out_size) {
    const float* x  = (const float*)d_in[0];
    const float* u3 = (const float*)d_in[1];
    // Defensive: if input order is swapped (u3 is 14*3 = 42 elems)
    if (n_in >= 2 && in_sizes[0] == NQ * 3 && in_sizes[1] == BATCH * NQ) {
        const float* t = x; x = u3; u3 = t;
    }
    float* out = (float*)d_out;
    qulinear_kernel<<<(BATCH + 255) / 256, 256>>>(x, u3, out);
}

// round 4
// speedup vs baseline: 1.5628x; 1.5628x over previous
#include <cuda_runtime.h>
#include <math.h>

#define NQ 14
#define BATCH 2048
#define BLK 64

struct Masks {
    unsigned S[NQ];   // S_w: row w of M^-1 (subset over u, bit u = 1<<u)
    unsigned T[NQ];   // T_w: column w of M
    int      k4[NQ];  // |S_w & T_w| mod 4
};

// Compile-time: compose the 28 CNOT permutations (GF(2)-linear), build M,
// invert it over GF(2), and extract S/T/k masks. __host__ __device__ so it
// is usable in device-side constexpr contexts without --expt-relaxed-constexpr.
__host__ __device__ constexpr Masks compute_masks() {
    Masks ms{};
    unsigned M[NQ] = {};
    for (int u = 0; u < NQ; ++u) {
        unsigned j = 1u << (13 - u);
        for (int step = 2; step >= 1; --step)
            for (int c = NQ - 1; c >= 0; --c) {
                int t = (c + step) % NQ;
                if ((j >> (13 - c)) & 1u) j ^= 1u << (13 - t);
            }
        for (int w = 0; w < NQ; ++w)
            if ((j >> (13 - w)) & 1u) M[w] |= 1u << u;
    }
    for (int w = 0; w < NQ; ++w) {
        unsigned t = 0;
        for (int r = 0; r < NQ; ++r)
            if ((M[r] >> w) & 1u) t |= 1u << r;
        ms.T[w] = t;
    }
    unsigned A[NQ] = {};
    unsigned I[NQ] = {};
    for (int r = 0; r < NQ; ++r) { A[r] = M[r]; I[r] = 1u << r; }
    for (int col = 0; col < NQ; ++col) {
        int piv = col;
        while (((A[piv] >> col) & 1u) == 0u) ++piv;
        unsigned ta = A[col]; A[col] = A[piv]; A[piv] = ta;
        unsigned ti = I[col]; I[col] = I[piv]; I[piv] = ti;
        for (int r = 0; r < NQ; ++r)
            if (r != col && ((A[r] >> col) & 1u)) { A[r] ^= A[col]; I[r] ^= I[col]; }
    }
    for (int w = 0; w < NQ; ++w) ms.S[w] = I[w];
    for (int w = 0; w < NQ; ++w) {
        unsigned xm = ms.S[w] & ms.T[w];
        int cnt = 0;
        for (int b = 0; b < NQ; ++b) cnt += (int)((xm >> b) & 1u);
        ms.k4[w] = cnt & 3;
    }
    return ms;
}

// k4 packed 2 bits per qubit into one word (28 bits used).
__host__ __device__ constexpr unsigned pack_k4() {
    Masks ms = compute_masks();
    unsigned p = 0;
    for (int w = 0; w < NQ; ++w) p |= ((unsigned)ms.k4[w]) << (2 * w);
    return p;
}

// ---- Template-folded product accumulation: masks are template-level
// constants, so excluded factors are removed by the front end itself. ----

template<int W, int U>
__device__ __forceinline__ void accum(float& Zp, float& R1, float& R2,
                                      const float* z, const float* G, const float* y) {
    constexpr bool iS = (compute_masks().S[W] >> U) & 1u;
    constexpr bool iT = (compute_masks().T[W] >> U) & 1u;
    if constexpr (iS && iT) { Zp *= z[U]; R1 *= G[U]; R2 *= y[U]; }
    else if constexpr (iS)  { Zp *= z[U]; R2 *= z[U]; }
    else if constexpr (iT)  { R1 *= G[U]; R2 *= G[U]; }
    if constexpr (U + 1 < NQ) accum<W, U + 1>(Zp, R1, R2, z, G, y);
}

template<int W>
__device__ __forceinline__ void emit(int b, const float* z, const float* G, const float* y,
                                     const float* c1, const float* c2, const float* c3,
                                     float* out) {
    float Zp = 1.0f, R1 = 1.0f, R2 = 1.0f;
    accum<W, 0>(Zp, R1, R2, z, G, y);
    out[b * NQ + W] = c1[W] * Zp - c2[W] * R1 - c3[W] * R2;
    if constexpr (W + 1 < NQ) emit<W + 1>(b, z, G, y, c1, c2, c3, out);
}

__global__ void __launch_bounds__(BLK)
qulinear_kernel(const float* __restrict__ x, const float* __restrict__ u3,
                float* __restrict__ out) {
    __shared__ float c1[NQ], c2[NQ], c3[NQ];
    int tid = threadIdx.x;
    if (tid < NQ) {
        float th  = u3[tid * 3 + 0];
        float lam = u3[tid * 3 + 2];   // phi cancels in U3^dag Z U3
        float st, ct, sl, cl;
        sincosf(th, &st, &ct);
        sincosf(lam, &sl, &cl);
        constexpr unsigned K4P = pack_k4();
        int k = (int)((K4P >> (2 * tid)) & 3u);
        // cos(lam + k*pi/2)
        float f = (k == 0) ? cl : (k == 1) ? -sl : (k == 2) ? -cl : sl;
        c1[tid] = ct;
        c2[tid] = st * cl;
        c3[tid] = st * f;
    }
    __syncthreads();

    int b = blockIdx.x * BLK + tid;

    float z[NQ], G[NQ], y[NQ];
#pragma unroll
    for (int u = 0; u < NQ; ++u) {
        float xv = x[b * NQ + u];
        float x2 = xv * xv;
        float i1 = rsqrtf(fmaf(xv, xv, 1.0f));   // 1/sqrt(1+x^2)
        float i2 = rsqrtf(fmaf(x2, x2, 1.0f));   // 1/sqrt(1+x^4)
        float gi = i1 * i2;
        z[u] = -xv * i1;
        G[u] = gi;
        y[u] = x2 * gi;
    }

    emit<0>(b, z, G, y, c1, c2, c3, out);
}

extern "C" void kernel_launch(void* const* d_in, const int* in_sizes, int n_in,
                              void* d_out, int out_size) {
    const float* x  = (const float*)d_in[0];
    const float* u3 = (const float*)d_in[1];
    if (n_in >= 2 && in_sizes[0] == NQ * 3 && in_sizes[1] == BATCH * NQ) {
        const float* t = x; x = u3; u3 = t;
    }
    float* out = (float*)d_out;
    qulinear_kernel<<<BATCH / BLK, BLK>>>(x, u3, out);
}

// round 6
// speedup vs baseline: 1.6552x; 1.0591x over previous
#include <cuda_runtime.h>
#include <math.h>

#define NQ 14
#define BATCH 2048
#define ELEMS 16              // batch elements per block
#define BLK 256               // 16 elems x 16 threads (14 used per elem)
#define ACTIVE (ELEMS * NQ)   // 224

struct Masks {
    unsigned S[NQ];
    unsigned T[NQ];
    int      k4[NQ];
};

__host__ __device__ constexpr Masks compute_masks() {
    Masks ms{};
    unsigned M[NQ] = {};
    for (int u = 0; u < NQ; ++u) {
        unsigned j = 1u << (13 - u);
        for (int step = 2; step >= 1; --step)
            for (int c = NQ - 1; c >= 0; --c) {
                int t = (c + step) % NQ;
                if ((j >> (13 - c)) & 1u) j ^= 1u << (13 - t);
            }
        for (int w = 0; w < NQ; ++w)
            if ((j >> (13 - w)) & 1u) M[w] |= 1u << u;
    }
    for (int w = 0; w < NQ; ++w) {
        unsigned t = 0;
        for (int r = 0; r < NQ; ++r)
            if ((M[r] >> w) & 1u) t |= 1u << r;
        ms.T[w] = t;
    }
    unsigned A[NQ] = {};
    unsigned I[NQ] = {};
    for (int r = 0; r < NQ; ++r) { A[r] = M[r]; I[r] = 1u << r; }
    for (int col = 0; col < NQ; ++col) {
        int piv = col;
        while (((A[piv] >> col) & 1u) == 0u) ++piv;
        unsigned ta = A[col]; A[col] = A[piv]; A[piv] = ta;
        unsigned ti = I[col]; I[col] = I[piv]; I[piv] = ti;
        for (int r = 0; r < NQ; ++r)
            if (r != col && ((A[r] >> col) & 1u)) { A[r] ^= A[col]; I[r] ^= I[col]; }
    }
    for (int w = 0; w < NQ; ++w) ms.S[w] = I[w];
    for (int w = 0; w < NQ; ++w) {
        unsigned xm = ms.S[w] & ms.T[w];
        int cnt = 0;
        for (int b = 0; b < NQ; ++b) cnt += (int)((xm >> b) & 1u);
        ms.k4[w] = cnt & 3;
    }
    return ms;
}

// Compile-time folded product accumulation for output qubit W.
template<int W, int U>
__device__ __forceinline__ void accum(float& Zp, float& R1, float& R2,
                                      const float* z, const float* G, const float* y) {
    constexpr bool iS = (compute_masks().S[W] >> U) & 1u;
    constexpr bool iT = (compute_masks().T[W] >> U) & 1u;
    if constexpr (iS && iT) { Zp *= z[U]; R1 *= G[U]; R2 *= y[U]; }
    else if constexpr (iS)  { Zp *= z[U]; R2 *= z[U]; }
    else if constexpr (iT)  { R1 *= G[U]; R2 *= G[U]; }
    if constexpr (U + 1 < NQ) accum<W, U + 1>(Zp, R1, R2, z, G, y);
}

template<int W>
__device__ __forceinline__ float emitW(const float* z, const float* G, const float* y,
                                       float th, float lam) {
    float st, ct, sl, cl;
    sincosf(th, &st, &ct);
    sincosf(lam, &sl, &cl);
    constexpr int k = compute_masks().k4[W];
    float f = (k == 0) ? cl : (k == 1) ? -sl : (k == 2) ? -cl : sl;
    float Zp = 1.0f, R1 = 1.0f, R2 = 1.0f;
    accum<W, 0>(Zp, R1, R2, z, G, y);
    return ct * Zp - (st * cl) * R1 - (st * f) * R2;
}

__global__ void __launch_bounds__(BLK)
qulinear_kernel(const float* __restrict__ x, const float* __restrict__ u3,
                float* __restrict__ out) {
    __shared__ float zs[ACTIVE], Gs[ACTIVE], ys[ACTIVE];

    const int tid = threadIdx.x;
    const int b0  = blockIdx.x * ELEMS;        // first batch element of block

    // Phase-2 identity (computed early so u3 loads can issue before the barrier)
    const int w = tid >> 4;                    // output qubit  (0..13 valid)
    const int e = tid & 15;                    // element index within block
    float th = 0.0f, lam = 0.0f;
    if (tid < ACTIVE && w < NQ) {
        th  = __ldg(&u3[w * 3 + 0]);
        lam = __ldg(&u3[w * 3 + 2]);           // phi cancels in U3^dag Z U3
    }

    // Phase 1: one (element, qubit) scalar per thread, coalesced x load.
    if (tid < ACTIVE) {
        float xv = x[b0 * NQ + tid];           // layout [e][u], contiguous
        float x2 = xv * xv;
        float i1 = rsqrtf(fmaf(xv, xv, 1.0f)); // 1/sqrt(1+x^2)
        float i2 = rsqrtf(fmaf(x2, x2, 1.0f)); // 1/sqrt(1+x^4)
        float gi = i1 * i2;
        zs[tid] = -xv * i1;
        Gs[tid] = gi;
        ys[tid] = x2 * gi;
    }
    __syncthreads();

    // Phase 2: one output per thread. w uniform per half-warp -> cheap switch.
    if (tid < ACTIVE) {
        const float* z = zs + e * NQ;
        const float* G = Gs + e * NQ;
        const float* y = ys + e * NQ;
        float r;
        switch (w) {
            case 0:  r = emitW<0>(z, G, y, th, lam);  break;
            case 1:  r = emitW<1>(z, G, y, th, lam);  break;
            case 2:  r = emitW<2>(z, G, y, th, lam);  break;
            case 3:  r = emitW<3>(z, G, y, th, lam);  break;
            case 4:  r = emitW<4>(z, G, y, th, lam);  break;
            case 5:  r = emitW<5>(z, G, y, th, lam);  break;
            case 6:  r = emitW<6>(z, G, y, th, lam);  break;
            case 7:  r = emitW<7>(z, G, y, th, lam);  break;
            case 8:  r = emitW<8>(z, G, y, th, lam);  break;
            case 9:  r = emitW<9>(z, G, y, th, lam);  break;
            case 10: r = emitW<10>(z, G, y, th, lam); break;
            case 11: r = emitW<11>(z, G, y, th, lam); break;
            case 12: r = emitW<12>(z, G, y, th, lam); break;
            default: r = emitW<13>(z, G, y, th, lam); break;
        }
        out[(b0 + e) * NQ + w] = r;
    }
}

extern "C" void kernel_launch(void* const* d_in, const int* in_sizes, int n_in,
                              void* d_out, int out_size) {
    const float* x  = (const float*)d_in[0];
    const float* u3 = (const float*)d_in[1];
    if (n_in >= 2 && in_sizes[0] == NQ * 3 && in_sizes[1] == BATCH * NQ) {
        const float* t = x; x = u3; u3 = t;
    }
    float* out = (float*)d_out;
    qulinear_kernel<<<BATCH / ELEMS, BLK>>>(x, u3, out);
}

// round 7
// speedup vs baseline: 1.7500x; 1.0573x over previous
#include <cuda_runtime.h>
#include <math.h>

#define NQ 14
#define BATCH 2048
#define ELEMS 16              // batch elements per block
#define BLK 256               // 16 elems x 16 threads (14 used per elem)
#define ACTIVE (ELEMS * NQ)   // 224

struct Masks {
    unsigned S[NQ];
    unsigned T[NQ];
    int      k4[NQ];
};

__host__ __device__ constexpr Masks compute_masks() {
    Masks ms{};
    unsigned M[NQ] = {};
    for (int u = 0; u < NQ; ++u) {
        unsigned j = 1u << (13 - u);
        for (int step = 2; step >= 1; --step)
            for (int c = NQ - 1; c >= 0; --c) {
                int t = (c + step) % NQ;
                if ((j >> (13 - c)) & 1u) j ^= 1u << (13 - t);
            }
        for (int w = 0; w < NQ; ++w)
            if ((j >> (13 - w)) & 1u) M[w] |= 1u << u;
    }
    for (int w = 0; w < NQ; ++w) {
        unsigned t = 0;
        for (int r = 0; r < NQ; ++r)
            if ((M[r] >> w) & 1u) t |= 1u << r;
        ms.T[w] = t;
    }
    unsigned A[NQ] = {};
    unsigned I[NQ] = {};
    for (int r = 0; r < NQ; ++r) { A[r] = M[r]; I[r] = 1u << r; }
    for (int col = 0; col < NQ; ++col) {
        int piv = col;
        while (((A[piv] >> col) & 1u) == 0u) ++piv;
        unsigned ta = A[col]; A[col] = A[piv]; A[piv] = ta;
        unsigned ti = I[col]; I[col] = I[piv]; I[piv] = ti;
        for (int r = 0; r < NQ; ++r)
            if (r != col && ((A[r] >> col) & 1u)) { A[r] ^= A[col]; I[r] ^= I[col]; }
    }
    for (int w = 0; w < NQ; ++w) ms.S[w] = I[w];
    for (int w = 0; w < NQ; ++w) {
        unsigned xm = ms.S[w] & ms.T[w];
        int cnt = 0;
        for (int b = 0; b < NQ; ++b) cnt += (int)((xm >> b) & 1u);
        ms.k4[w] = cnt & 3;
    }
    return ms;
}

__host__ __device__ constexpr unsigned pack_k4() {
    Masks ms = compute_masks();
    unsigned p = 0;
    for (int w = 0; w < NQ; ++w) p |= ((unsigned)ms.k4[w]) << (2 * w);
    return p;
}

// Compile-time folded product accumulation for output qubit W.
template<int W, int U>
__device__ __forceinline__ void accum(float& Zp, float& R1, float& R2,
                                      const float* z, const float* G, const float* y) {
    constexpr bool iS = (compute_masks().S[W] >> U) & 1u;
    constexpr bool iT = (compute_masks().T[W] >> U) & 1u;
    if constexpr (iS && iT) { Zp *= z[U]; R1 *= G[U]; R2 *= y[U]; }
    else if constexpr (iS)  { Zp *= z[U]; R2 *= z[U]; }
    else if constexpr (iT)  { R1 *= G[U]; R2 *= G[U]; }
    if constexpr (U + 1 < NQ) accum<W, U + 1>(Zp, R1, R2, z, G, y);
}

// Products only — coefficients are precomputed before the barrier.
template<int W>
__device__ __forceinline__ float emitW(const float* z, const float* G, const float* y,
                                       float c1, float c2, float c3) {
    float Zp = 1.0f, R1 = 1.0f, R2 = 1.0f;
    accum<W, 0>(Zp, R1, R2, z, G, y);
    return c1 * Zp - c2 * R1 - c3 * R2;
}

__global__ void __launch_bounds__(BLK)
qulinear_kernel(const float* __restrict__ x, const float* __restrict__ u3,
                float* __restrict__ out) {
    __shared__ float zs[ACTIVE], Gs[ACTIVE], ys[ACTIVE];

    const int tid = threadIdx.x;
    const int b0  = blockIdx.x * ELEMS;

    const int w = tid >> 4;                    // output qubit for phase 2
    const int e = tid & 15;                    // element index for phase 2
    const bool act = (tid < ACTIVE);

    // ---- Issue both global loads up front so they overlap ----
    float xv = 0.0f, th = 0.0f, lam = 0.0f;
    if (act) {
        xv  = x[b0 * NQ + tid];                // coalesced [e][u] layout
        th  = __ldg(&u3[w * 3 + 0]);
        lam = __ldg(&u3[w * 3 + 2]);           // phi cancels in U3^dag Z U3
    }

    // ---- Coefficients (U3) computed in the LDG shadow, before the barrier ----
    float c1 = 0.0f, c2 = 0.0f, c3 = 0.0f;
    if (act) {
        float st, ct, sl, cl;
        sincosf(th, &st, &ct);
        sincosf(lam, &sl, &cl);
        constexpr unsigned K4P = pack_k4();
        int k = (int)((K4P >> (2 * w)) & 3u);
        // cos(lam + k*pi/2), branch-free
        float f = (k == 0) ? cl : (k == 1) ? -sl : (k == 2) ? -cl : sl;
        c1 = ct;
        c2 = st * cl;
        c3 = st * f;
    }

    // ---- Phase 1: per-(element,qubit) scalars into smem ----
    if (act) {
        float x2 = xv * xv;
        float i1 = rsqrtf(fmaf(xv, xv, 1.0f)); // 1/sqrt(1+x^2)
        float i2 = rsqrtf(fmaf(x2, x2, 1.0f)); // 1/sqrt(1+x^4)
        float gi = i1 * i2;
        zs[tid] = -xv * i1;
        Gs[tid] = gi;
        ys[tid] = x2 * gi;
    }
    __syncthreads();

    // ---- Phase 2: one output per thread; masks folded at compile time ----
    if (act) {
        const float* z = zs + e * NQ;
        const float* G = Gs + e * NQ;
        const float* y = ys + e * NQ;
        float r;
        switch (w) {   // uniform per half-warp -> 2-way divergence only
            case 0:  r = emitW<0>(z, G, y, c1, c2, c3);  break;
            case 1:  r = emitW<1>(z, G, y, c1, c2, c3);  break;
            case 2:  r = emitW<2>(z, G, y, c1, c2, c3);  break;
            case 3:  r = emitW<3>(z, G, y, c1, c2, c3);  break;
            case 4:  r = emitW<4>(z, G, y, c1, c2, c3);  break;
            case 5:  r = emitW<5>(z, G, y, c1, c2, c3);  break;
            case 6:  r = emitW<6>(z, G, y, c1, c2, c3);  break;
            case 7:  r = emitW<7>(z, G, y, c1, c2, c3);  break;
            case 8:  r = emitW<8>(z, G, y, c1, c2, c3);  break;
            case 9:  r = emitW<9>(z, G, y, c1, c2, c3);  break;
            case 10: r = emitW<10>(z, G, y, c1, c2, c3); break;
            case 11: r = emitW<11>(z, G, y, c1, c2, c3); break;
            case 12: r = emitW<12>(z, G, y, c1, c2, c3); break;
            default: r = emitW<13>(z, G, y, c1, c2, c3); break;
        }
        out[(b0 + e) * NQ + w] = r;
    }
}

extern "C" void kernel_launch(void* const* d_in, const int* in_sizes, int n_in,
                              void* d_out, int out_size) {
    const float* x  = (const float*)d_in[0];
    const float* u3 = (const float*)d_in[1];
    if (n_in >= 2 && in_sizes[0] == NQ * 3 && in_sizes[1] == BATCH * NQ) {
        const float* t = x; x = u3; u3 = t;
    }
    float* out = (float*)d_out;
    qulinear_kernel<<<BATCH / ELEMS, BLK>>>(x, u3, out);
}